// round 2
// baseline (speedup 1.0000x reference)
#include <cuda_runtime.h>
#include <math.h>

#define HID 2048
#define VOC 256
#define SEQ 2048
#define G3  (3 * HID)          // 6144

// ---- recurrence kernel geometry ----
#define RGRID     147          // ceil(2048/14); <= SM count -> co-resident
#define RJ        14           // h-indices per CTA
#define NROWS     42           // 3 gates * RJ
#define RTPB      512          // 16 warps
#define SMEM_ROWS 26           // weight rows resident in SMEM
#define RECUR_SMEM ((SMEM_ROWS * HID + HID + 3 * 48) * 4)  // 221760 B

// ---- device scratch (static allocation is the sanctioned scratch path) ----
__device__ float g_gi_enc[VOC * G3];
__device__ float g_gi_dec[VOC * G3];
__device__ float g_h[HID];
__device__ float g_dec_hs[(size_t)SEQ * HID];
__device__ unsigned int g_cnt;
__device__ unsigned int g_rel;

// ============================================================
// Generic C[M,N] = A[M,K] * B[N,K]^T + bias[N]   (all fp32)
// 64x64 tile, BK=16, 256 threads, 4x4 per thread.
// All problem dims here are multiples of 64/16 -> no guards.
// ============================================================
__global__ __launch_bounds__(256) void gemm_nt(
    const float* __restrict__ A, const float* __restrict__ B,
    const float* __restrict__ bias, float* __restrict__ C,
    int M, int N, int K)
{
    __shared__ float As[16][68];
    __shared__ float Bs[16][68];

    const int tid = threadIdx.x;
    const int m0 = blockIdx.y * 64;
    const int n0 = blockIdx.x * 64;
    const int ml = tid >> 2;            // 0..63
    const int k4 = (tid & 3) << 2;      // 0,4,8,12
    const int ty = tid >> 4;            // 0..15
    const int tx = tid & 15;            // 0..15

    float acc[4][4] = {};

    for (int kb = 0; kb < K; kb += 16) {
        float4 a = *(const float4*)&A[(size_t)(m0 + ml) * K + kb + k4];
        float4 b = *(const float4*)&B[(size_t)(n0 + ml) * K + kb + k4];
        As[k4 + 0][ml] = a.x; As[k4 + 1][ml] = a.y;
        As[k4 + 2][ml] = a.z; As[k4 + 3][ml] = a.w;
        Bs[k4 + 0][ml] = b.x; Bs[k4 + 1][ml] = b.y;
        Bs[k4 + 2][ml] = b.z; Bs[k4 + 3][ml] = b.w;
        __syncthreads();
#pragma unroll
        for (int k = 0; k < 16; k++) {
            float4 av = *(const float4*)&As[k][ty << 2];
            float4 bv = *(const float4*)&Bs[k][tx << 2];
            acc[0][0] += av.x * bv.x; acc[0][1] += av.x * bv.y;
            acc[0][2] += av.x * bv.z; acc[0][3] += av.x * bv.w;
            acc[1][0] += av.y * bv.x; acc[1][1] += av.y * bv.y;
            acc[1][2] += av.y * bv.z; acc[1][3] += av.y * bv.w;
            acc[2][0] += av.z * bv.x; acc[2][1] += av.z * bv.y;
            acc[2][2] += av.z * bv.z; acc[2][3] += av.z * bv.w;
            acc[3][0] += av.w * bv.x; acc[3][1] += av.w * bv.y;
            acc[3][2] += av.w * bv.z; acc[3][3] += av.w * bv.w;
        }
        __syncthreads();
    }

#pragma unroll
    for (int i = 0; i < 4; i++) {
        const int m = m0 + (ty << 2) + i;
#pragma unroll
        for (int j = 0; j < 4; j++) {
            const int n = n0 + (tx << 2) + j;
            C[(size_t)m * N + n] = acc[i][j] + bias[n];
        }
    }
}

// ============================================================
// Barrier-state reset (run before each recurrence launch so the
// monotone counters are valid across graph replays).
// ============================================================
__global__ void reset_kernel()
{
    if (threadIdx.x == 0) { g_cnt = 0u; g_rel = 0u; }
}

// ============================================================
// Persistent GRU recurrence: 147 CTAs x 512 threads, all co-resident.
// CTA c owns h-indices [14c, 14c+14). Local row lr = gate*14 + j,
// lr in [0,42). Residency: lr 0..15 and 32..41 in SMEM (slots lr /
// lr-16), lr 16..31 in registers (one row per warp, 64 regs/lane).
// Per step: stage h (ldcg, L2), per-warp fp32 dots (float4 LDS,
// conflict-free), shfl-reduce, 14 gate threads, global barrier.
// ============================================================
__global__ __launch_bounds__(RTPB, 1) void recur_kernel(
    const int* __restrict__ inputs, const int* __restrict__ targets,
    const float* __restrict__ enc_w_hh, const float* __restrict__ enc_b_hh,
    const float* __restrict__ dec_w_hh, const float* __restrict__ dec_b_hh)
{
    extern __shared__ float smem[];
    float* sw  = smem;                       // [26][2048]
    float* shh = sw + SMEM_ROWS * HID;       // [2048]
    float* sgh = shh + HID;                  // [48]
    float* sbh = sgh + 48;                   // [48]
    float* sgi = sbh + 48;                   // [48]

    const int tid   = threadIdx.x;
    const int w     = tid >> 5;
    const int lane  = tid & 31;
    const int cta   = blockIdx.x;
    const int jbase = cta * RJ;

    float4 wreg[16];

    for (int phase = 0; phase < 2; phase++) {
        const float* Whh    = phase ? dec_w_hh : enc_w_hh;
        const float* Bhh    = phase ? dec_b_hh : enc_b_hh;
        const float* gi_tab = phase ? g_gi_dec : g_gi_enc;

        // ---- load SMEM-resident weight rows ----
        for (int s = 0; s < SMEM_ROWS; s++) {
            const int lr   = (s < 16) ? s : s + 16;
            const int gate = lr / RJ;
            const int jg   = jbase + (lr % RJ);
            if (jg < HID) {
                const float4* src = (const float4*)(Whh + (size_t)(gate * HID + jg) * HID);
                float4* dst = (float4*)(sw + s * HID);
                for (int idx = tid; idx < HID / 4; idx += RTPB) dst[idx] = src[idx];
            } else {
                for (int idx = tid; idx < HID; idx += RTPB) sw[s * HID + idx] = 0.f;
            }
        }
        // ---- load register-resident row (lr = w + 16) ----
        {
            const int lr   = w + 16;
            const int gate = lr / RJ;
            const int jg   = jbase + (lr % RJ);
            if (jg < HID) {
                const float4* src = (const float4*)(Whh + (size_t)(gate * HID + jg) * HID);
#pragma unroll
                for (int i = 0; i < 16; i++) wreg[i] = src[i * 32 + lane];
            } else {
#pragma unroll
                for (int i = 0; i < 16; i++) wreg[i] = make_float4(0.f, 0.f, 0.f, 0.f);
            }
        }
        // ---- biases ----
        if (tid < NROWS) {
            const int gate = tid / RJ;
            const int jg   = jbase + (tid % RJ);
            sbh[tid] = (jg < HID) ? Bhh[gate * HID + jg] : 0.f;
        }
        __syncthreads();

        for (int t = 0; t < SEQ; t++) {
            // 1. stage h into SMEM (L2-only loads: L1 may hold stale h)
            if (phase == 0 && t == 0) {
                for (int idx = tid; idx < HID; idx += RTPB) shh[idx] = 0.f;
            } else {
                float4* dst = (float4*)shh;
                const float4* src = (const float4*)g_h;
                for (int idx = tid; idx < HID / 4; idx += RTPB)
                    dst[idx] = __ldcg(src + idx);
            }
            // 2. prefetch gi (latency hidden under the dot loop)
            if (tid < NROWS) {
                const int tok  = (phase == 0) ? inputs[t] : (t == 0 ? 0 : targets[1]);
                const int gate = tid / RJ;
                const int jg   = jbase + (tid % RJ);
                sgi[tid] = (jg < HID)
                    ? gi_tab[(size_t)tok * G3 + gate * HID + jg] : 0.f;
            }
            __syncthreads();

            // 3. dot products: warp w -> rows {w (SMEM), w+16 (RF), w+32 (SMEM, w<10)}
            {
                const float4* hv = (const float4*)shh;
                const float4* pa = (const float4*)(sw + w * HID);
                const float4* pc = (const float4*)(sw + (w + 16) * HID); // slot for lr=w+32
                float4 aA = make_float4(0.f, 0.f, 0.f, 0.f);
                float4 aB = aA, aC = aA;
#pragma unroll
                for (int i = 0; i < 16; i++) {
                    const int n = (i << 5) + lane;
                    float4 h4 = hv[n];
                    float4 x  = pa[n];
                    aA.x += x.x * h4.x; aA.y += x.y * h4.y;
                    aA.z += x.z * h4.z; aA.w += x.w * h4.w;
                    float4 y = wreg[i];
                    aB.x += y.x * h4.x; aB.y += y.y * h4.y;
                    aB.z += y.z * h4.z; aB.w += y.w * h4.w;
                    if (w < 10) {
                        float4 zz = pc[n];
                        aC.x += zz.x * h4.x; aC.y += zz.y * h4.y;
                        aC.z += zz.z * h4.z; aC.w += zz.w * h4.w;
                    }
                }
                float sA = (aA.x + aA.y) + (aA.z + aA.w);
                float sB = (aB.x + aB.y) + (aB.z + aB.w);
                float sC = (aC.x + aC.y) + (aC.z + aC.w);
#pragma unroll
                for (int o = 16; o > 0; o >>= 1) {
                    sA += __shfl_down_sync(0xffffffffu, sA, o);
                    sB += __shfl_down_sync(0xffffffffu, sB, o);
                    sC += __shfl_down_sync(0xffffffffu, sC, o);
                }
                if (lane == 0) {
                    sgh[w]      = sA;
                    sgh[w + 16] = sB;
                    if (w < 10) sgh[w + 32] = sC;
                }
            }
            __syncthreads();

            // 4. gates (one thread per owned h-index)
            if (tid < RJ) {
                const int jg = jbase + tid;
                if (jg < HID) {
                    const float ghr = sgh[tid]          + sbh[tid];
                    const float ghz = sgh[RJ + tid]     + sbh[RJ + tid];
                    const float ghn = sgh[2 * RJ + tid] + sbh[2 * RJ + tid];
                    const float ir  = sgi[tid];
                    const float iz  = sgi[RJ + tid];
                    const float in_ = sgi[2 * RJ + tid];
                    const float r = 1.f / (1.f + expf(-(ir + ghr)));
                    const float z = 1.f / (1.f + expf(-(iz + ghz)));
                    const float n = tanhf(in_ + r * ghn);
                    const float hn = (1.f - z) * n + z * shh[jg];
                    g_h[jg] = hn;
                    if (phase) g_dec_hs[(size_t)t * HID + jg] = hn;
                }
            }
            __threadfence();   // release h stores before barrier arrival
            __syncthreads();

            // 5. chip-wide barrier (monotone counter + release flag)
            const unsigned target = (unsigned)(phase * SEQ + t) + 1u;
            if (tid == 0) {
                const unsigned old = atomicAdd(&g_cnt, 1u);
                if (old == (unsigned)RGRID * target - 1u) {
                    __threadfence();
                    atomicExch(&g_rel, target);
                } else {
                    while (*((volatile unsigned*)&g_rel) < target) {}
                    __threadfence();
                }
            }
            __syncthreads();
        }
    }
}

// ============================================================
// Launch: gi tables (2 GEMMs) -> reset -> persistent recurrence
//         -> output projection GEMM.
// ============================================================
extern "C" void kernel_launch(void* const* d_in, const int* in_sizes, int n_in,
                              void* d_out, int out_size)
{
    const int*   inputs   = (const int*)d_in[0];
    const int*   targets  = (const int*)d_in[1];
    const float* emb      = (const float*)d_in[2];
    const float* enc_w_ih = (const float*)d_in[3];
    const float* enc_w_hh = (const float*)d_in[4];
    const float* enc_b_ih = (const float*)d_in[5];
    const float* enc_b_hh = (const float*)d_in[6];
    const float* dec_w_ih = (const float*)d_in[7];
    const float* dec_w_hh = (const float*)d_in[8];
    const float* dec_b_ih = (const float*)d_in[9];
    const float* dec_b_hh = (const float*)d_in[10];
    const float* fc_w     = (const float*)d_in[11];
    const float* fc_b     = (const float*)d_in[12];
    float* out = (float*)d_out;

    float *gi_enc_p, *gi_dec_p, *dec_hs_p;
    cudaGetSymbolAddress((void**)&gi_enc_p, g_gi_enc);
    cudaGetSymbolAddress((void**)&gi_dec_p, g_gi_dec);
    cudaGetSymbolAddress((void**)&dec_hs_p, g_dec_hs);
    cudaFuncSetAttribute(recur_kernel,
                         cudaFuncAttributeMaxDynamicSharedMemorySize, RECUR_SMEM);

    dim3 tb(256);
    // gi tables: [256, 6144] = emb @ w_ih^T + b_ih
    gemm_nt<<<dim3(G3 / 64, VOC / 64), tb>>>(emb, enc_w_ih, enc_b_ih,
                                             gi_enc_p, VOC, G3, HID);
    gemm_nt<<<dim3(G3 / 64, VOC / 64), tb>>>(emb, dec_w_ih, dec_b_ih,
                                             gi_dec_p, VOC, G3, HID);
    reset_kernel<<<1, 32>>>();
    recur_kernel<<<RGRID, RTPB, RECUR_SMEM>>>(inputs, targets,
                                              enc_w_hh, enc_b_hh,
                                              dec_w_hh, dec_b_hh);
    // logits: [2048, 256] = dec_hs @ fc_w^T + fc_b
    gemm_nt<<<dim3(VOC / 64, SEQ / 64), tb>>>(dec_hs_p, fc_w, fc_b,
                                              out, SEQ, VOC, HID);
}